// round 14
// baseline (speedup 1.0000x reference)
#include <cuda_runtime.h>
#include <cuda_fp16.h>
#include <cstdint>

#define B_    1024
#define T_    512
#define OBS_  64
#define H_    256
#define A_    16
#define NCTA  (B_ / 8)

// h history: per CTA, per step, 1024 u32 fragment words (fp16 pairs). 256 MB.
__device__ uint32_t g_h[(size_t)NCTA * T_ * 1024];

// ---------- helpers ----------
__device__ __forceinline__ uint32_t f2h2(float lo, float hi) {
    uint32_t r;
    asm("cvt.rn.f16x2.f32 %0, %1, %2;" : "=r"(r) : "f"(hi), "f"(lo));
    return r;
}
__device__ __forceinline__ float sigf(float x) {
    float t;
    asm("tanh.approx.f32 %0, %1;" : "=f"(t) : "f"(0.5f * x));
    return fmaf(0.5f, t, 0.5f);
}
// m16n8k16 row.col f32 += f16*f16
__device__ __forceinline__ void mma16816(float* c, const uint32_t* a,
                                         uint32_t b0, uint32_t b1) {
    asm("mma.sync.aligned.m16n8k16.row.col.f32.f16.f16.f32 "
        "{%0,%1,%2,%3}, {%4,%5,%6,%7}, {%8,%9}, {%0,%1,%2,%3};"
        : "+f"(c[0]), "+f"(c[1]), "+f"(c[2]), "+f"(c[3])
        : "r"(a[0]), "r"(a[1]), "r"(a[2]), "r"(a[3]), "r"(b0), "r"(b1));
}

// ============================================================================
// Persistent RNN kernel. 128 CTAs x 256 thr (8 warps). CTA owns 8 batch rows.
// Phase 1 (serial): h-recurrence only. 40 MMAs/warp/step in 8 accum chains,
//   h_t streamed to g_h (1 STG.128/thread/step). One barrier per step.
// Phase 2 (parallel): warp w computes pre_o for t in [64w, 64w+64) from g_h,
//   writes pre_o into out[b][t][a] slots.
// Phase 3: 128 threads run the o-EMA scan over t in place.
// B-frag smem layout (fragment order): uint2 per (kt, lq, col b) -> 1 LDS.64.
// ============================================================================
extern "C" __global__ void __launch_bounds__(256, 1)
rnn_kernel(const float* __restrict__ obs,  const float* __restrict__ W_in,
           const float* __restrict__ W_h,  const float* __restrict__ b_h,
           const float* __restrict__ W_out, const float* __restrict__ b_out,
           float* __restrict__ out)
{
    __shared__ uint32_t s_hp[2][1024];     // h   frags [buf][((kt*4+q)*8+b)*2+ws]
    __shared__ uint32_t s_ob[2][256];      // obs frags [buf][...] kt=0..3

    const int tid  = threadIdx.x;
    const int w    = tid >> 5, lane = tid & 31;
    const int ln   = lane >> 2, lq = lane & 3;     // groupID / inGroup
    const int jbase = w * 32 + ln;
    const int bg0  = blockIdx.x * 8;

    // ---- persistent A-fragments: W_h [2 m-tiles][16 k-tiles][4 regs] ----
    uint32_t ah[2][16][4];
#pragma unroll
    for (int kt = 0; kt < 16; kt++) {
        const int k0 = kt * 16 + lq * 2;
#pragma unroll
        for (int m = 0; m < 2; m++) {
            const int r0 = jbase + m * 16, r1 = r0 + 8;
            float2 v00 = *(const float2*)&W_h[r0 * 256 + k0];
            float2 v10 = *(const float2*)&W_h[r1 * 256 + k0];
            float2 v01 = *(const float2*)&W_h[r0 * 256 + k0 + 8];
            float2 v11 = *(const float2*)&W_h[r1 * 256 + k0 + 8];
            ah[m][kt][0] = f2h2(v00.x, v00.y);
            ah[m][kt][1] = f2h2(v10.x, v10.y);
            ah[m][kt][2] = f2h2(v01.x, v01.y);
            ah[m][kt][3] = f2h2(v11.x, v11.y);
        }
    }
    // ---- W_in fragments [2][4][4] ----
    uint32_t ai[2][4][4];
#pragma unroll
    for (int kt = 0; kt < 4; kt++) {
        const int k0 = kt * 16 + lq * 2;
#pragma unroll
        for (int m = 0; m < 2; m++) {
            const int r0 = jbase + m * 16, r1 = r0 + 8;
            float2 v00 = *(const float2*)&W_in[r0 * 64 + k0];
            float2 v10 = *(const float2*)&W_in[r1 * 64 + k0];
            float2 v01 = *(const float2*)&W_in[r0 * 64 + k0 + 8];
            float2 v11 = *(const float2*)&W_in[r1 * 64 + k0 + 8];
            ai[m][kt][0] = f2h2(v00.x, v00.y);
            ai[m][kt][1] = f2h2(v10.x, v10.y);
            ai[m][kt][2] = f2h2(v01.x, v01.y);
            ai[m][kt][3] = f2h2(v11.x, v11.y);
        }
    }

    float bh[4];
#pragma unroll
    for (int ri = 0; ri < 4; ri++) bh[ri] = b_h[jbase + 8 * ri];

    // EMA state (fp32, exact)
    float hs[4][2];
#pragma unroll
    for (int ri = 0; ri < 4; ri++) { hs[ri][0] = 0.0f; hs[ri][1] = 0.0f; }

    // zero h buffers (h_{-1}=0); preload obs(0) into buf 0
#pragma unroll
    for (int i = 0; i < 8; i++)
        ((uint32_t*)s_hp)[tid + i * 256] = 0u;
    {
        const int b = tid & 7, pk0 = tid >> 3;
        float2 v = *(const float2*)&obs[((size_t)(bg0 + b) * T_) * OBS_ + pk0 * 2];
        const int kt = pk0 >> 3, q = pk0 & 3, ws = (pk0 >> 2) & 1;
        s_ob[0][((kt * 4 + q) * 8 + b) * 2 + ws] = f2h2(v.x, v.y);
    }
    __syncthreads();

    const int pb = tid & 7, pk = tid >> 3;         // obs prefetch identity
    const int okt = pk >> 3, oq = pk & 3, ows = (pk >> 2) & 1;
    const int eq = ln >> 1, ehalf = ln & 1;        // epilogue store geometry
    uint32_t* ghc = g_h + (size_t)blockIdx.x * T_ * 1024;

    // ================= Phase 1: recurrent loop =================
    for (int t = 0; t <= T_; t++) {
        const int cur = t & 1, nxt = cur ^ 1;

        // stream h_{t-1} (s_hp[cur]) to gmem — fire-and-forget
        if (t >= 1) {
            const uint4* src = (const uint4*)s_hp[cur];
            ((uint4*)(ghc + (size_t)(t - 1) * 1024))[tid] = src[tid];
        }

        if (t < T_) {
            // prefetch obs(t+1)
            const int tn = (t + 1 < T_) ? t + 1 : T_ - 1;
            float2 opf = *(const float2*)
                &obs[((size_t)(bg0 + pb) * T_ + tn) * OBS_ + pk * 2];

            // ---- h-GEMM: 8 accumulation chains (m x kt&3), depth 5 ----
            float c[2][4][4];
#pragma unroll
            for (int m = 0; m < 2; m++)
#pragma unroll
                for (int ch = 0; ch < 4; ch++)
#pragma unroll
                    for (int e = 0; e < 4; e++) c[m][ch][e] = 0.0f;
            {
                const uint2* hp2 = (const uint2*)s_hp[cur];
#pragma unroll
                for (int kt = 0; kt < 16; kt++) {
                    uint2 bb = hp2[(kt * 4 + lq) * 8 + ln];
                    mma16816(c[0][kt & 3], ah[0][kt], bb.x, bb.y);
                    mma16816(c[1][kt & 3], ah[1][kt], bb.x, bb.y);
                }
                const uint2* ob2 = (const uint2*)s_ob[cur];
#pragma unroll
                for (int kt = 0; kt < 4; kt++) {
                    uint2 bb = ob2[(kt * 4 + lq) * 8 + ln];
                    mma16816(c[0][kt], ai[0][kt], bb.x, bb.y);
                    mma16816(c[1][kt], ai[1][kt], bb.x, bb.y);
                }
            }

            // ---- epilogue: merge chains, EMA, publish h_t ----
            {
                uint16_t* hp16 = (uint16_t*)s_hp[nxt];
#pragma unroll
                for (int m = 0; m < 2; m++) {
#pragma unroll
                    for (int e = 0; e < 4; e++) {
                        const int ri = m * 2 + (e >> 1), par = e & 1;
                        float pre = (c[m][0][e] + c[m][1][e]) +
                                    (c[m][2][e] + c[m][3][e]) + bh[ri];
                        float hn = 0.9f * hs[ri][par] + 0.1f * sigf(pre);
                        hs[ri][par] = hn;
                        const int kt = w * 2 + (ri >> 1), ws = ri & 1;
                        const int b = 2 * lq + par;
                        hp16[((((kt * 4 + eq) * 8 + b) * 2 + ws) << 1) + ehalf] =
                            __half_as_ushort(__float2half_rn(hn));
                    }
                }
                // publish obs(t+1)
                s_ob[nxt][((okt * 4 + oq) * 8 + pb) * 2 + ows] = f2h2(opf.x, opf.y);
            }
        }

        __syncthreads();   // single barrier per step
    }

    // ---- finals: h (tuple order: out[B,T,A], h[1,B,H], o[1,B,A]) ----
    const size_t HOFF = (size_t)B_ * T_ * A_;
    const size_t OOFF = HOFF + (size_t)B_ * H_;
#pragma unroll
    for (int ri = 0; ri < 4; ri++) {
        const int j = jbase + 8 * ri;
#pragma unroll
        for (int par = 0; par < 2; par++) {
            const int b = 2 * lq + par;
            out[HOFF + (size_t)(bg0 + b) * H_ + j] = hs[ri][par];
        }
    }

    // ================= Phase 2: pre_o GEMM (parallel over t) =================
    // W_out fragments, full k: [16 kt][4] (ah/ai now dead -> regs reused)
    {
        uint32_t ao2[16][4];
#pragma unroll
        for (int kt = 0; kt < 16; kt++) {
            const int k0 = kt * 16 + lq * 2;
            float2 v00 = *(const float2*)&W_out[ln * 256 + k0];
            float2 v10 = *(const float2*)&W_out[(ln + 8) * 256 + k0];
            float2 v01 = *(const float2*)&W_out[ln * 256 + k0 + 8];
            float2 v11 = *(const float2*)&W_out[(ln + 8) * 256 + k0 + 8];
            ao2[kt][0] = f2h2(v00.x, v00.y);
            ao2[kt][1] = f2h2(v10.x, v10.y);
            ao2[kt][2] = f2h2(v01.x, v01.y);
            ao2[kt][3] = f2h2(v11.x, v11.y);
        }
        // warp w owns t in [64w, 64w+64)
        for (int tt = 0; tt < 64; tt++) {
            const int t = w * 64 + tt;
            const uint2* hb = (const uint2*)(ghc + (size_t)t * 1024);
            float co[4] = {0, 0, 0, 0};
#pragma unroll
            for (int kt = 0; kt < 16; kt++) {
                uint2 bb = hb[(kt * 4 + lq) * 8 + ln];
                mma16816(co, ao2[kt], bb.x, bb.y);
            }
            // pre_o -> out[b][t][a]
            out[((size_t)(bg0 + 2 * lq)     * T_ + t) * A_ + ln]     = co[0];
            out[((size_t)(bg0 + 2 * lq + 1) * T_ + t) * A_ + ln]     = co[1];
            out[((size_t)(bg0 + 2 * lq)     * T_ + t) * A_ + ln + 8] = co[2];
            out[((size_t)(bg0 + 2 * lq + 1) * T_ + t) * A_ + ln + 8] = co[3];
        }
    }
    __syncthreads();

    // ================= Phase 3: o-EMA scan (128 threads, one (b,a) each) ====
    if (tid < 128) {
        const int b = tid >> 4, a = tid & 15;
        const float bo = b_out[a];
        float o = 0.0f;
        float* p = out + ((size_t)(bg0 + b) * T_) * A_ + a;
#pragma unroll 8
        for (int t = 0; t < T_; t++) {
            float v = p[t * A_];
            o = 0.9f * o + 0.1f * sigf(v + bo);
            p[t * A_] = o;
        }
        out[OOFF + (size_t)(bg0 + b) * A_ + a] = o;
    }
}

// ============================================================================
extern "C" void kernel_launch(void* const* d_in, const int* in_sizes, int n_in,
                              void* d_out, int out_size) {
    const float* obs   = (const float*)d_in[0];
    const float* W_in  = (const float*)d_in[1];
    const float* W_h   = (const float*)d_in[2];
    const float* b_h   = (const float*)d_in[3];
    const float* W_out = (const float*)d_in[4];
    const float* b_out = (const float*)d_in[5];
    float* out = (float*)d_out;

    rnn_kernel<<<NCTA, 256>>>(obs, W_in, W_h, b_h, W_out, b_out, out);
}